// round 14
// baseline (speedup 1.0000x reference)
#include <cuda_runtime.h>
#include <cuda_fp16.h>
#include <math.h>
#include <stdint.h>

#define N_NODES 100000
#define N_EDGES_MAX 1600000
#define HIDDEN  128
#define NFILT   64
#define CUTOFF  8.0f
#define TABLE_N 8192
#define N_TILES ((N_NODES + 127) / 128)  // 782
#define LDW     136                      // smem fp16 row stride
#define NB      256                      // scan chunks
#define CH      391                      // ceil(100000/256)
#define XCONV_B0 161                     // setup kernel block ranges
#define HIST_B0  (XCONV_B0 + 1024)       // 1185

// ---- device scratch (allocation-free) ----
__device__ __align__(16) __half g_xh[N_NODES * HIDDEN];    // fp16 copy of x (25.6MB)
__device__ __align__(16) __half g_aggh[N_NODES * HIDDEN];  // fp16 aggregate (25.6MB)
__device__ float g_table[TABLE_N];
__device__ float g_oscale[HIDDEN];
__device__ float g_oshift[HIDDEN];
__device__ float g_fsmin;
__device__ float g_fsq;                 // 32767 / range
__device__ float g_fsstep;              // range / 32767
// fp16 weights, transposed: [n][k]
__device__ __align__(16) __half g_W1[HIDDEN * HIDDEN];
__device__ __align__(16) __half g_W2[HIDDEN * HIDDEN];
// CSR
__device__ int   g_cnt[N_NODES];        // zero at entry; scan3 re-zeroes
__device__ int   g_rowptr[N_NODES + 1];
__device__ int   g_cur[N_NODES];
__device__ int   g_part[NB];
__device__ int   g_poff[NB];
__device__ int   g_ctr;                 // scan12 completion counter (self-resetting)
__device__ uint32_t g_eord[N_EDGES_MAX]; // packed edge: col[0:17) | q[17:32)

// ================= helpers =================
__device__ __forceinline__ uint32_t smem_u32(const void* p) {
    uint32_t a;
    asm("{ .reg .u64 t; cvta.to.shared.u64 t, %1; cvt.u32.u64 %0, t; }" : "=r"(a) : "l"(p));
    return a;
}
__device__ __forceinline__ uint32_t f16pack(float x0, float x1) {
    uint32_t p;  // lower half = x0
    asm("cvt.rn.f16x2.f32 %0, %1, %2;" : "=r"(p) : "f"(x1), "f"(x0));
    return p;
}
__device__ __forceinline__ float softplus_f(float x) {
    return log1pf(expf(-fabsf(x))) + fmaxf(x, 0.f);
}
// packed f32x2 (B300 FFMA2)
__device__ __forceinline__ unsigned long long pk2f(float lo, float hi) {
    unsigned long long r;
    asm("mov.b64 %0, {%1, %2};" : "=l"(r) : "f"(lo), "f"(hi));
    return r;
}
__device__ __forceinline__ float2 upk2f(unsigned long long v) {
    float2 f;
    asm("mov.b64 {%0, %1}, %2;" : "=f"(f.x), "=f"(f.y) : "l"(v));
    return f;
}
__device__ __forceinline__ unsigned long long ffma2p(unsigned long long a,
                                                     unsigned long long b,
                                                     unsigned long long c) {
    unsigned long long d;
    asm("fma.rn.f32x2 %0, %1, %2, %3;" : "=l"(d) : "l"(a), "l"(b), "l"(c));
    return d;
}
// half2 -> packed f32x2 (2x F2F + pack)
__device__ __forceinline__ unsigned long long h2tof2(uint32_t h) {
    unsigned long long r;
    asm("{\n\t"
        ".reg .b16 l, hh;\n\t"
        ".reg .f32 fl, fh;\n\t"
        "mov.b32 {l, hh}, %1;\n\t"
        "cvt.f32.f16 fl, l;\n\t"
        "cvt.f32.f16 fh, hh;\n\t"
        "mov.b64 %0, {fl, fh};\n\t"
        "}" : "=l"(r) : "r"(h));
    return r;
}
__device__ __forceinline__ void ldsm_x4(uint32_t* r, uint32_t addr) {
    asm volatile("ldmatrix.sync.aligned.m8n8.x4.shared.b16 {%0,%1,%2,%3}, [%4];"
                 : "=r"(r[0]), "=r"(r[1]), "=r"(r[2]), "=r"(r[3]) : "r"(addr));
}
__device__ __forceinline__ void mma16816(float* d, const uint32_t* a, const uint32_t* b) {
    asm volatile("mma.sync.aligned.m16n8k16.row.col.f32.f16.f16.f32 "
                 "{%0,%1,%2,%3}, {%4,%5,%6,%7}, {%8,%9}, {%0,%1,%2,%3};"
                 : "+f"(d[0]), "+f"(d[1]), "+f"(d[2]), "+f"(d[3])
                 : "r"(a[0]), "r"(a[1]), "r"(a[2]), "r"(a[3]), "r"(b[0]), "r"(b[1]));
}

// ================= fused setup + histogram kernel =================
// block 0: BN fold | [1,33): table | [33,161): wprep | [161,1185): xconv | rest: hist
__global__ __launch_bounds__(256) void setup_kernel(
        const float* __restrict__ x, const int* __restrict__ ei, int E,
        const float* __restrict__ Wf1, const float* __restrict__ bf1,
        const float* __restrict__ Wf2, const float* __restrict__ bf2,
        const float* __restrict__ Wi1, const float* __restrict__ Wi2,
        const float* __restrict__ bi2, const float* __restrict__ gamma,
        const float* __restrict__ beta, const float* __restrict__ mmean,
        const float* __restrict__ mvar) {
    int b = blockIdx.x, tid = threadIdx.x;

    if (b >= HIST_B0) {                       // histogram range
        int e = (b - HIST_B0) * 256 + tid;
        if (e < E) atomicAdd(&g_cnt[ei[e]], 1);
        return;
    }
    if (b == 0) {
        if (tid < HIDDEN) {
            float sc = gamma[tid] * rsqrtf(mvar[tid] + 1e-3f);
            g_oscale[tid] = sc;
            g_oshift[tid] = (bi2[tid] - mmean[tid]) * sc + beta[tid];
        }
        return;
    }
    if (b < 33) {
        __shared__ float swsum[NFILT];
        __shared__ float sbsum;
        if (tid < NFILT) {
            float s = 0.f;
            for (int f = 0; f < NFILT; f++) s += Wf2[tid * NFILT + f];
            swsum[tid] = s;
        }
        if (tid == 0) {
            float s = 0.f;
            for (int f = 0; f < NFILT; f++) s += bf2[f];
            sbsum = s;
        }
        __syncthreads();
        int t = (b - 1) * 256 + tid;
        float w = (float)t * (CUTOFF / (float)(TABLE_N - 1));
        float sc = w * (2.0f / CUTOFF) - 1.0f;
        float s = sbsum;
        #pragma unroll 8
        for (int g = 0; g < NFILT; g++)
            s += tanhf(sc * __ldg(&Wf1[g]) + __ldg(&bf1[g])) * swsum[g];
        float cut = 0.5f * (cospif(w * (1.0f / CUTOFF)) + 1.0f);
        g_table[t] = s * cut;
        return;
    }
    if (b < XCONV_B0) {
        int idx = (b - 33) * 256 + tid;       // over 2*128*128 = 32768
        int w = idx / (HIDDEN * HIDDEN);
        int r = idx % (HIDDEN * HIDDEN);
        int n = r / HIDDEN, k = r % HIDDEN;
        float v = (w ? Wi2 : Wi1)[k * HIDDEN + n];
        (w ? g_W2 : g_W1)[n * HIDDEN + k] = __float2half_rn(v);
        return;
    }
    // x -> fp16, strided over 3.2M float4
    const int n4 = N_NODES * HIDDEN / 4;
    int start = (b - XCONV_B0) * 256 + tid;
    int stride = (HIST_B0 - XCONV_B0) * 256;
    for (int i = start; i < n4; i += stride) {
        float4 v = ((const float4*)x)[i];
        ((uint2*)g_xh)[i] = make_uint2(f16pack(v.x, v.y), f16pack(v.z, v.w));
    }
}

// ================= CSR build =================
__global__ __launch_bounds__(256) void scan12_kernel() {
    __shared__ int red[256];
    __shared__ float fmn[256], fmx[256];
    __shared__ int isLast;
    int b = blockIdx.x, t = threadIdx.x;
    int base = b * CH;
    int s = 0;
    for (int i = t; i < CH; i += 256) {
        int gi = base + i;
        s += (gi < N_NODES) ? g_cnt[gi] : 0;
    }
    red[t] = s;
    __syncthreads();
    for (int d = 128; d > 0; d >>= 1) {
        if (t < d) red[t] += red[t + d];
        __syncthreads();
    }
    if (t == 0) {
        g_part[b] = red[0];
        __threadfence();
        isLast = (atomicAdd(&g_ctr, 1) == NB - 1);
    }
    __syncthreads();
    if (!isLast) return;
    int v = g_part[t];
    red[t] = v;
    __syncthreads();
    for (int d = 1; d < 256; d <<= 1) {
        int u = (t >= d) ? red[t - d] : 0;
        __syncthreads();
        red[t] += u;
        __syncthreads();
    }
    g_poff[t] = red[t] - v;
    // table min/max for fs quantization
    float mn = 3.4e38f, mx = -3.4e38f;
    for (int i = t; i < TABLE_N; i += 256) {
        float tv = g_table[i];
        mn = fminf(mn, tv); mx = fmaxf(mx, tv);
    }
    fmn[t] = mn; fmx[t] = mx;
    __syncthreads();
    for (int d = 128; d > 0; d >>= 1) {
        if (t < d) {
            fmn[t] = fminf(fmn[t], fmn[t + d]);
            fmx[t] = fmaxf(fmx[t], fmx[t + d]);
        }
        __syncthreads();
    }
    if (t == 0) {
        float range = fmx[0] - fmn[0];
        g_fsmin = fmn[0];
        g_fsq = (range > 0.f) ? (32767.f / range) : 0.f;
        g_fsstep = range * (1.f / 32767.f);
        g_ctr = 0;
    }
}
__global__ void scan3_kernel(int E) {
    __shared__ int s[512];
    int b = blockIdx.x, t = threadIdx.x;
    int base = b * CH;
    int gi = base + t;
    int c = (t < CH && gi < N_NODES) ? g_cnt[gi] : 0;
    s[t] = c;
    __syncthreads();
    for (int d = 1; d < 512; d <<= 1) {
        int v = (t >= d) ? s[t - d] : 0;
        __syncthreads();
        s[t] += v;
        __syncthreads();
    }
    if (t < CH && gi < N_NODES) {
        int ex = g_poff[b] + s[t] - c;
        g_rowptr[gi] = ex;
        g_cur[gi] = ex;
        g_cnt[gi] = 0;
    }
    if (b == NB - 1 && t == 0) g_rowptr[N_NODES] = E;
}
__global__ void reorder_kernel(const int* __restrict__ ei, const float* __restrict__ ew,
                               int E) {
    int e = blockIdx.x * blockDim.x + threadIdx.x;
    if (e >= E) return;
    int row = ei[e], col = ei[E + e];
    float w = ew[e];
    float fs = 0.f;
    if (w <= CUTOFF) {
        float u = w * ((float)(TABLE_N - 1) / CUTOFF);
        int i = (int)u;
        if (i > TABLE_N - 2) i = TABLE_N - 2;
        float fr = u - (float)i;
        float t0 = g_table[i];
        fs = t0 + fr * (g_table[i + 1] - t0);
    }
    int q = (int)rintf((fs - g_fsmin) * g_fsq);
    q = (q < 0) ? 0 : (q > 32767 ? 32767 : q);
    int pos = atomicAdd(&g_cur[row], 1);
    g_eord[pos] = (uint32_t)col | ((uint32_t)q << 17);
}

// ================= aggregate: decode-once + packed FFMA2 =================
// Lanes: 2 edge-parities (h) x 16 uint4 chunks (c). Lanes 0..7 decode records,
// floats are shfl-broadcast. Accumulate as 4 packed f32x2 via fma.rn.f32x2.
__global__ __launch_bounds__(256) void aggregate_kernel() {
    int node = (blockIdx.x * blockDim.x + threadIdx.x) >> 5;
    int lane = threadIdx.x & 31;
    if (node >= N_NODES) return;
    int h = lane >> 4;
    int c = lane & 15;
    int s = g_rowptr[node], e = g_rowptr[node + 1];
    float fsmin = g_fsmin, fsstep = g_fsstep;

    unsigned long long a0 = 0ULL, a1 = 0ULL, a2 = 0ULL, a3 = 0ULL;

    int b = s;
    for (; b + 8 <= e; b += 8) {
        int cdec = 0; float fdec = 0.f;
        if (lane < 8) {
            uint32_t rec = g_eord[b + lane];
            cdec = (int)(rec & 0x1FFFFu);
            fdec = fsmin + (float)(rec >> 17) * fsstep;
        }
        uint4 v[4]; unsigned long long fp[4];
        #pragma unroll
        for (int p = 0; p < 4; p++) {
            int j = p * 2 + h;
            int col = __shfl_sync(0xFFFFFFFFu, cdec, j);
            float f = __shfl_sync(0xFFFFFFFFu, fdec, j);
            fp[p] = pk2f(f, f);
            v[p] = ((const uint4*)g_xh)[(size_t)col * 16 + c];
        }
        #pragma unroll
        for (int p = 0; p < 4; p++) {
            a0 = ffma2p(h2tof2(v[p].x), fp[p], a0);
            a1 = ffma2p(h2tof2(v[p].y), fp[p], a1);
            a2 = ffma2p(h2tof2(v[p].z), fp[p], a2);
            a3 = ffma2p(h2tof2(v[p].w), fp[p], a3);
        }
    }
    if (b < e) {
        int n = e - b;
        int cdec = 0; float fdec = 0.f;
        if (lane < n) {
            uint32_t rec = g_eord[b + lane];
            cdec = (int)(rec & 0x1FFFFu);
            fdec = fsmin + (float)(rec >> 17) * fsstep;
        }
        uint4 v[4]; unsigned long long fp[4]; bool act[4];
        #pragma unroll
        for (int p = 0; p < 4; p++) {
            int j = p * 2 + h;
            int col = __shfl_sync(0xFFFFFFFFu, cdec, j);
            float f = __shfl_sync(0xFFFFFFFFu, fdec, j);
            fp[p] = pk2f(f, f);
            act[p] = (j < n);
            if (act[p]) v[p] = ((const uint4*)g_xh)[(size_t)col * 16 + c];
        }
        #pragma unroll
        for (int p = 0; p < 4; p++) {
            if (act[p]) {
                a0 = ffma2p(h2tof2(v[p].x), fp[p], a0);
                a1 = ffma2p(h2tof2(v[p].y), fp[p], a1);
                a2 = ffma2p(h2tof2(v[p].z), fp[p], a2);
                a3 = ffma2p(h2tof2(v[p].w), fp[p], a3);
            }
        }
    }
    // combine edge-parities
    float2 f0 = upk2f(a0), f1 = upk2f(a1), f2 = upk2f(a2), f3 = upk2f(a3);
    float accs[8] = {f0.x, f0.y, f1.x, f1.y, f2.x, f2.y, f3.x, f3.y};
    #pragma unroll
    for (int q = 0; q < 8; q++)
        accs[q] += __shfl_xor_sync(0xFFFFFFFFu, accs[q], 16);
    if (h == 0) {
        uint4 o;
        o.x = f16pack(accs[0], accs[1]);
        o.y = f16pack(accs[2], accs[3]);
        o.z = f16pack(accs[4], accs[5]);
        o.w = f16pack(accs[6], accs[7]);
        ((uint4*)g_aggh)[(size_t)node * 16 + c] = o;
    }
}

// ================= tensor-core (HMMA fp16) MLP =================
#define SA_O   0
#define SW1_O  17408
#define SW2_O  34816
#define SM_F16_TOTAL 52224
#define SMEM_MMA (SM_F16_TOTAL * 2 + 3 * 512)

__device__ __forceinline__ void gemm_pass(float acc[16][4], uint32_t aBase, uint32_t wBase,
                                          int arow, int acol, int brow, int bcol) {
    #pragma unroll
    for (int k0 = 0; k0 < 128; k0 += 16) {
        uint32_t a[4];
        ldsm_x4(a, aBase + (uint32_t)(arow * LDW + k0 + acol) * 2u);
        #pragma unroll
        for (int nt = 0; nt < 8; nt++) {
            uint32_t b[4];
            ldsm_x4(b, wBase + (uint32_t)((nt * 16 + brow) * LDW + k0 + bcol) * 2u);
            mma16816(acc[nt * 2],     a, b);
            mma16816(acc[nt * 2 + 1], a, b + 2);
        }
    }
}

__global__ __launch_bounds__(256, 2) void mlp_mma_kernel(const float* __restrict__ bi1,
                                                         float* __restrict__ out) {
    extern __shared__ __half sm[];
    float* sBias  = (float*)(sm + SM_F16_TOTAL);
    float* sScale = sBias + 128;
    float* sShift = sBias + 256;

    int tid = threadIdx.x;
    int lane = tid & 31, wp = tid >> 5;
    int m0 = wp * 16;

    for (int i = tid; i < 2 * 128 * 16; i += 256) {
        int a = i >> 11;
        int r = (i >> 4) & 127;
        int q = i & 15;
        const uint4* src = (const uint4*)(a == 0 ? g_W1 : g_W2);
        int dst = (a == 0 ? SW1_O : SW2_O);
        *(uint4*)&sm[dst + r * LDW + q * 8] = src[r * 16 + q];
    }
    if (tid < 128) {
        sBias[tid]  = bi1[tid];
        sScale[tid] = g_oscale[tid];
        sShift[tid] = g_oshift[tid];
    }
    __syncthreads();

    uint32_t sb  = smem_u32(sm);
    uint32_t sbA = sb + SA_O * 2;
    uint32_t sb1 = sb + SW1_O * 2, sb2 = sb + SW2_O * 2;

    int arow = m0 + (lane & 15);
    int acol = (lane >> 4) << 3;
    int brow = (lane & 7) + ((lane >> 4) << 3);
    int bcol = ((lane >> 3) & 1) << 3;
    int cb = (lane & 3) * 2;
    int r0 = m0 + (lane >> 2);

    for (int tile = blockIdx.x; tile < N_TILES; tile += gridDim.x) {
        int rbase = tile * 128;

        for (int i = tid; i < 128 * 32; i += 256) {
            int r = i >> 5, c = i & 31;
            int row = rbase + r;
            uint2 v = make_uint2(0u, 0u);
            if (row < N_NODES) v = ((const uint2*)g_aggh)[(size_t)row * 32 + c];
            *(uint2*)&sm[SA_O + r * LDW + c * 4] = v;
        }
        __syncthreads();

        float acc[16][4];
        #pragma unroll
        for (int nt = 0; nt < 16; nt++) {
            float b0 = sBias[nt * 8 + cb], b1 = sBias[nt * 8 + cb + 1];
            acc[nt][0] = b0; acc[nt][1] = b1; acc[nt][2] = b0; acc[nt][3] = b1;
        }
        gemm_pass(acc, sbA, sb1, arow, acol, brow, bcol);
        __syncwarp();

        #pragma unroll
        for (int nt = 0; nt < 16; nt++) {
            int c = nt * 8 + cb;
            float h0 = softplus_f(acc[nt][0]);
            float h1 = softplus_f(acc[nt][1]);
            float h2 = softplus_f(acc[nt][2]);
            float h3 = softplus_f(acc[nt][3]);
            *(uint32_t*)&sm[SA_O + r0 * LDW + c]       = f16pack(h0, h1);
            *(uint32_t*)&sm[SA_O + (r0 + 8) * LDW + c] = f16pack(h2, h3);
        }
        __syncwarp();

        #pragma unroll
        for (int nt = 0; nt < 16; nt++) {
            acc[nt][0] = 0.f; acc[nt][1] = 0.f; acc[nt][2] = 0.f; acc[nt][3] = 0.f;
        }
        gemm_pass(acc, sbA, sb2, arow, acol, brow, bcol);

        int g0 = rbase + r0;
        #pragma unroll
        for (int nt = 0; nt < 16; nt++) {
            int c = nt * 8 + cb;
            float s0 = sScale[c], s1 = sScale[c + 1];
            float t0 = sShift[c], t1 = sShift[c + 1];
            if (g0 < N_NODES)
                *(float2*)&out[(size_t)g0 * 128 + c] =
                    make_float2(acc[nt][0] * s0 + t0, acc[nt][1] * s1 + t1);
            if (g0 + 8 < N_NODES)
                *(float2*)&out[(size_t)(g0 + 8) * 128 + c] =
                    make_float2(acc[nt][2] * s0 + t0, acc[nt][3] * s1 + t1);
        }
        __syncthreads();
    }
}

extern "C" void kernel_launch(void* const* d_in, const int* in_sizes, int n_in,
                              void* d_out, int out_size) {
    const float* x     = (const float*)d_in[0];
    const int*   ei    = (const int*)  d_in[1];
    const float* ew    = (const float*)d_in[2];
    const float* Wf1   = (const float*)d_in[4];
    const float* bf1   = (const float*)d_in[5];
    const float* Wf2   = (const float*)d_in[6];
    const float* bf2   = (const float*)d_in[7];
    const float* Wi1   = (const float*)d_in[8];
    const float* bi1   = (const float*)d_in[9];
    const float* Wi2   = (const float*)d_in[10];
    const float* bi2   = (const float*)d_in[11];
    const float* gamma = (const float*)d_in[12];
    const float* beta  = (const float*)d_in[13];
    const float* mmean = (const float*)d_in[14];
    const float* mvar  = (const float*)d_in[15];
    int E = in_sizes[2];
    float* out = (float*)d_out;

    int setup_grid = HIST_B0 + (E + 255) / 256;
    setup_kernel<<<setup_grid, 256>>>(x, ei, E, Wf1, bf1, Wf2, bf2, Wi1, Wi2,
                                      bi2, gamma, beta, mmean, mvar);
    scan12_kernel<<<NB, 256>>>();
    scan3_kernel<<<NB, 512>>>(E);
    reorder_kernel<<<(E + 255) / 256, 256>>>(ei, ew, E);
    aggregate_kernel<<<(N_NODES * 32 + 255) / 256, 256>>>();

    cudaFuncSetAttribute(mlp_mma_kernel, cudaFuncAttributeMaxDynamicSharedMemorySize,
                         SMEM_MMA);
    mlp_mma_kernel<<<296, 256, SMEM_MMA>>>(bi1, out);
}

// round 15
// speedup vs baseline: 1.0371x; 1.0371x over previous
#include <cuda_runtime.h>
#include <cuda_fp16.h>
#include <math.h>
#include <stdint.h>

#define N_NODES 100000
#define N_EDGES_MAX 1600000
#define HIDDEN  128
#define NFILT   64
#define CUTOFF  8.0f
#define TABLE_N 8192
#define N_TILES ((N_NODES + 127) / 128)  // 782
#define LDW     136                      // smem fp16 row stride
#define NB      256                      // scan chunks
#define CH      391                      // ceil(100000/256)
#define XCONV_B0 161                     // setup kernel block ranges
#define HIST_B0  (XCONV_B0 + 1024)       // 1185

// ---- device scratch (allocation-free) ----
__device__ __align__(16) __half g_xh[N_NODES * HIDDEN];    // fp16 copy of x (25.6MB)
__device__ __align__(16) __half g_aggh[N_NODES * HIDDEN];  // fp16 aggregate (25.6MB)
__device__ float g_table[TABLE_N];
__device__ float g_oscale[HIDDEN];
__device__ float g_oshift[HIDDEN];
__device__ float g_fsmin;
__device__ float g_fsq;                 // 32767 / range
__device__ float g_fsstep;              // range / 32767
// fp16 weights, transposed: [n][k]
__device__ __align__(16) __half g_W1[HIDDEN * HIDDEN];
__device__ __align__(16) __half g_W2[HIDDEN * HIDDEN];
// CSR
__device__ int   g_cnt[N_NODES];        // zero at entry; scan3 re-zeroes
__device__ int   g_rowptr[N_NODES + 1];
__device__ int   g_rank[N_EDGES_MAX];   // per-edge within-row rank (from hist)
__device__ int   g_part[NB];
__device__ int   g_poff[NB];
__device__ int   g_ctr;                 // scan12 completion counter (self-resetting)
__device__ uint32_t g_eord[N_EDGES_MAX]; // packed edge: col[0:17) | q[17:32)

// ================= helpers =================
__device__ __forceinline__ uint32_t smem_u32(const void* p) {
    uint32_t a;
    asm("{ .reg .u64 t; cvta.to.shared.u64 t, %1; cvt.u32.u64 %0, t; }" : "=r"(a) : "l"(p));
    return a;
}
__device__ __forceinline__ uint32_t f16pack(float x0, float x1) {
    uint32_t p;  // lower half = x0
    asm("cvt.rn.f16x2.f32 %0, %1, %2;" : "=r"(p) : "f"(x1), "f"(x0));
    return p;
}
__device__ __forceinline__ float softplus_f(float x) {
    return log1pf(expf(-fabsf(x))) + fmaxf(x, 0.f);
}
__device__ __forceinline__ void ldsm_x4(uint32_t* r, uint32_t addr) {
    asm volatile("ldmatrix.sync.aligned.m8n8.x4.shared.b16 {%0,%1,%2,%3}, [%4];"
                 : "=r"(r[0]), "=r"(r[1]), "=r"(r[2]), "=r"(r[3]) : "r"(addr));
}
__device__ __forceinline__ void mma16816(float* d, const uint32_t* a, const uint32_t* b) {
    asm volatile("mma.sync.aligned.m16n8k16.row.col.f32.f16.f16.f32 "
                 "{%0,%1,%2,%3}, {%4,%5,%6,%7}, {%8,%9}, {%0,%1,%2,%3};"
                 : "+f"(d[0]), "+f"(d[1]), "+f"(d[2]), "+f"(d[3])
                 : "r"(a[0]), "r"(a[1]), "r"(a[2]), "r"(a[3]), "r"(b[0]), "r"(b[1]));
}

// ================= fused setup + histogram kernel =================
// block 0: BN fold | [1,33): table | [33,161): wprep | [161,1185): xconv | rest: hist
__global__ __launch_bounds__(256) void setup_kernel(
        const float* __restrict__ x, const int* __restrict__ ei, int E,
        const float* __restrict__ Wf1, const float* __restrict__ bf1,
        const float* __restrict__ Wf2, const float* __restrict__ bf2,
        const float* __restrict__ Wi1, const float* __restrict__ Wi2,
        const float* __restrict__ bi2, const float* __restrict__ gamma,
        const float* __restrict__ beta, const float* __restrict__ mmean,
        const float* __restrict__ mvar) {
    int b = blockIdx.x, tid = threadIdx.x;

    if (b >= HIST_B0) {                       // histogram range (also records rank)
        int e = (b - HIST_B0) * 256 + tid;
        if (e < E) g_rank[e] = atomicAdd(&g_cnt[ei[e]], 1);
        return;
    }
    if (b == 0) {
        if (tid < HIDDEN) {
            float sc = gamma[tid] * rsqrtf(mvar[tid] + 1e-3f);
            g_oscale[tid] = sc;
            g_oshift[tid] = (bi2[tid] - mmean[tid]) * sc + beta[tid];
        }
        return;
    }
    if (b < 33) {
        __shared__ float swsum[NFILT];
        __shared__ float sbsum;
        if (tid < NFILT) {
            float s = 0.f;
            for (int f = 0; f < NFILT; f++) s += Wf2[tid * NFILT + f];
            swsum[tid] = s;
        }
        if (tid == 0) {
            float s = 0.f;
            for (int f = 0; f < NFILT; f++) s += bf2[f];
            sbsum = s;
        }
        __syncthreads();
        int t = (b - 1) * 256 + tid;
        float w = (float)t * (CUTOFF / (float)(TABLE_N - 1));
        float sc = w * (2.0f / CUTOFF) - 1.0f;
        float s = sbsum;
        #pragma unroll 8
        for (int g = 0; g < NFILT; g++)
            s += tanhf(sc * __ldg(&Wf1[g]) + __ldg(&bf1[g])) * swsum[g];
        float cut = 0.5f * (cospif(w * (1.0f / CUTOFF)) + 1.0f);
        g_table[t] = s * cut;
        return;
    }
    if (b < XCONV_B0) {
        int idx = (b - 33) * 256 + tid;       // over 2*128*128 = 32768
        int w = idx / (HIDDEN * HIDDEN);
        int r = idx % (HIDDEN * HIDDEN);
        int n = r / HIDDEN, k = r % HIDDEN;
        float v = (w ? Wi2 : Wi1)[k * HIDDEN + n];
        (w ? g_W2 : g_W1)[n * HIDDEN + k] = __float2half_rn(v);
        return;
    }
    // x -> fp16, strided over 3.2M float4
    const int n4 = N_NODES * HIDDEN / 4;
    int start = (b - XCONV_B0) * 256 + tid;
    int stride = (HIST_B0 - XCONV_B0) * 256;
    for (int i = start; i < n4; i += stride) {
        float4 v = ((const float4*)x)[i];
        ((uint2*)g_xh)[i] = make_uint2(f16pack(v.x, v.y), f16pack(v.z, v.w));
    }
}

// ================= CSR build =================
__global__ __launch_bounds__(256) void scan12_kernel() {
    __shared__ int red[256];
    __shared__ float fmn[256], fmx[256];
    __shared__ int isLast;
    int b = blockIdx.x, t = threadIdx.x;
    int base = b * CH;
    int s = 0;
    for (int i = t; i < CH; i += 256) {
        int gi = base + i;
        s += (gi < N_NODES) ? g_cnt[gi] : 0;
    }
    red[t] = s;
    __syncthreads();
    for (int d = 128; d > 0; d >>= 1) {
        if (t < d) red[t] += red[t + d];
        __syncthreads();
    }
    if (t == 0) {
        g_part[b] = red[0];
        __threadfence();
        isLast = (atomicAdd(&g_ctr, 1) == NB - 1);
    }
    __syncthreads();
    if (!isLast) return;
    int v = g_part[t];
    red[t] = v;
    __syncthreads();
    for (int d = 1; d < 256; d <<= 1) {
        int u = (t >= d) ? red[t - d] : 0;
        __syncthreads();
        red[t] += u;
        __syncthreads();
    }
    g_poff[t] = red[t] - v;
    // table min/max for fs quantization
    float mn = 3.4e38f, mx = -3.4e38f;
    for (int i = t; i < TABLE_N; i += 256) {
        float tv = g_table[i];
        mn = fminf(mn, tv); mx = fmaxf(mx, tv);
    }
    fmn[t] = mn; fmx[t] = mx;
    __syncthreads();
    for (int d = 128; d > 0; d >>= 1) {
        if (t < d) {
            fmn[t] = fminf(fmn[t], fmn[t + d]);
            fmx[t] = fmaxf(fmx[t], fmx[t + d]);
        }
        __syncthreads();
    }
    if (t == 0) {
        float range = fmx[0] - fmn[0];
        g_fsmin = fmn[0];
        g_fsq = (range > 0.f) ? (32767.f / range) : 0.f;
        g_fsstep = range * (1.f / 32767.f);
        g_ctr = 0;
    }
}
__global__ void scan3_kernel(int E) {
    __shared__ int s[512];
    int b = blockIdx.x, t = threadIdx.x;
    int base = b * CH;
    int gi = base + t;
    int c = (t < CH && gi < N_NODES) ? g_cnt[gi] : 0;
    s[t] = c;
    __syncthreads();
    for (int d = 1; d < 512; d <<= 1) {
        int v = (t >= d) ? s[t - d] : 0;
        __syncthreads();
        s[t] += v;
        __syncthreads();
    }
    if (t < CH && gi < N_NODES) {
        int ex = g_poff[b] + s[t] - c;
        g_rowptr[gi] = ex;
        g_cnt[gi] = 0;              // restore zero for next graph replay
    }
    if (b == NB - 1 && t == 0) g_rowptr[N_NODES] = E;
}
// atomic-free reorder: pos = rowptr[row] + rank[e]
__global__ void reorder_kernel(const int* __restrict__ ei, const float* __restrict__ ew,
                               int E) {
    int e = blockIdx.x * blockDim.x + threadIdx.x;
    if (e >= E) return;
    int row = ei[e], col = ei[E + e];
    float w = ew[e];
    float fs = 0.f;
    if (w <= CUTOFF) {
        float u = w * ((float)(TABLE_N - 1) / CUTOFF);
        int i = (int)u;
        if (i > TABLE_N - 2) i = TABLE_N - 2;
        float fr = u - (float)i;
        float t0 = g_table[i];
        fs = t0 + fr * (g_table[i + 1] - t0);
    }
    int q = (int)rintf((fs - g_fsmin) * g_fsq);
    q = (q < 0) ? 0 : (q > 32767 ? 32767 : q);
    int pos = g_rowptr[row] + g_rank[e];
    g_eord[pos] = (uint32_t)col | ((uint32_t)q << 17);
}

// ================= aggregate: one warp per node, packed-edge fp16 gather =========
// (round-12 version — best measured)
__global__ __launch_bounds__(256) void aggregate_kernel() {
    int node = (blockIdx.x * blockDim.x + threadIdx.x) >> 5;
    int lane = threadIdx.x & 31;
    if (node >= N_NODES) return;
    int h = lane >> 4;         // edge parity
    int c = lane & 15;         // uint4 chunk within row
    int s = g_rowptr[node], e = g_rowptr[node + 1];
    float fsmin = g_fsmin, fsstep = g_fsstep;

    float acc[8];
    #pragma unroll
    for (int q = 0; q < 8; q++) acc[q] = 0.f;

    int b = s;
    for (; b + 8 <= e; b += 8) {
        uint32_t rec = (lane < 8) ? g_eord[b + lane] : 0u;
        uint4 v[4]; float fv[4];
        #pragma unroll
        for (int p = 0; p < 4; p++) {
            uint32_t r = __shfl_sync(0xFFFFFFFFu, rec, p * 2 + h);
            int col = (int)(r & 0x1FFFFu);
            fv[p] = fsmin + (float)(r >> 17) * fsstep;
            v[p] = ((const uint4*)g_xh)[(size_t)col * 16 + c];
        }
        #pragma unroll
        for (int p = 0; p < 4; p++) {
            float f = fv[p];
            float2 a0 = __half22float2(*(const __half2*)&v[p].x);
            float2 a1 = __half22float2(*(const __half2*)&v[p].y);
            float2 a2 = __half22float2(*(const __half2*)&v[p].z);
            float2 a3 = __half22float2(*(const __half2*)&v[p].w);
            acc[0] += a0.x * f; acc[1] += a0.y * f;
            acc[2] += a1.x * f; acc[3] += a1.y * f;
            acc[4] += a2.x * f; acc[5] += a2.y * f;
            acc[6] += a3.x * f; acc[7] += a3.y * f;
        }
    }
    if (b < e) {
        int n = e - b;
        uint32_t rec = (lane < n) ? g_eord[b + lane] : 0u;
        uint4 v[4]; float fv[4]; bool act[4];
        #pragma unroll
        for (int p = 0; p < 4; p++) {
            int j = p * 2 + h;
            uint32_t r = __shfl_sync(0xFFFFFFFFu, rec, j);
            int col = (int)(r & 0x1FFFFu);
            fv[p] = fsmin + (float)(r >> 17) * fsstep;
            act[p] = (j < n);
            if (act[p]) v[p] = ((const uint4*)g_xh)[(size_t)col * 16 + c];
        }
        #pragma unroll
        for (int p = 0; p < 4; p++) {
            if (act[p]) {
                float f = fv[p];
                float2 a0 = __half22float2(*(const __half2*)&v[p].x);
                float2 a1 = __half22float2(*(const __half2*)&v[p].y);
                float2 a2 = __half22float2(*(const __half2*)&v[p].z);
                float2 a3 = __half22float2(*(const __half2*)&v[p].w);
                acc[0] += a0.x * f; acc[1] += a0.y * f;
                acc[2] += a1.x * f; acc[3] += a1.y * f;
                acc[4] += a2.x * f; acc[5] += a2.y * f;
                acc[6] += a3.x * f; acc[7] += a3.y * f;
            }
        }
    }
    #pragma unroll
    for (int q = 0; q < 8; q++)
        acc[q] += __shfl_xor_sync(0xFFFFFFFFu, acc[q], 16);
    if (h == 0) {
        uint4 o;
        o.x = f16pack(acc[0], acc[1]);
        o.y = f16pack(acc[2], acc[3]);
        o.z = f16pack(acc[4], acc[5]);
        o.w = f16pack(acc[6], acc[7]);
        ((uint4*)g_aggh)[(size_t)node * 16 + c] = o;
    }
}

// ================= tensor-core (HMMA fp16) MLP =================
#define SA_O   0
#define SW1_O  17408
#define SW2_O  34816
#define SM_F16_TOTAL 52224
#define SMEM_MMA (SM_F16_TOTAL * 2 + 3 * 512)

__device__ __forceinline__ void gemm_pass(float acc[16][4], uint32_t aBase, uint32_t wBase,
                                          int arow, int acol, int brow, int bcol) {
    #pragma unroll
    for (int k0 = 0; k0 < 128; k0 += 16) {
        uint32_t a[4];
        ldsm_x4(a, aBase + (uint32_t)(arow * LDW + k0 + acol) * 2u);
        #pragma unroll
        for (int nt = 0; nt < 8; nt++) {
            uint32_t b[4];
            ldsm_x4(b, wBase + (uint32_t)((nt * 16 + brow) * LDW + k0 + bcol) * 2u);
            mma16816(acc[nt * 2],     a, b);
            mma16816(acc[nt * 2 + 1], a, b + 2);
        }
    }
}

__global__ __launch_bounds__(256, 2) void mlp_mma_kernel(const float* __restrict__ bi1,
                                                         float* __restrict__ out) {
    extern __shared__ __half sm[];
    float* sBias  = (float*)(sm + SM_F16_TOTAL);
    float* sScale = sBias + 128;
    float* sShift = sBias + 256;

    int tid = threadIdx.x;
    int lane = tid & 31, wp = tid >> 5;
    int m0 = wp * 16;

    for (int i = tid; i < 2 * 128 * 16; i += 256) {
        int a = i >> 11;
        int r = (i >> 4) & 127;
        int q = i & 15;
        const uint4* src = (const uint4*)(a == 0 ? g_W1 : g_W2);
        int dst = (a == 0 ? SW1_O : SW2_O);
        *(uint4*)&sm[dst + r * LDW + q * 8] = src[r * 16 + q];
    }
    if (tid < 128) {
        sBias[tid]  = bi1[tid];
        sScale[tid] = g_oscale[tid];
        sShift[tid] = g_oshift[tid];
    }
    __syncthreads();

    uint32_t sb  = smem_u32(sm);
    uint32_t sbA = sb + SA_O * 2;
    uint32_t sb1 = sb + SW1_O * 2, sb2 = sb + SW2_O * 2;

    int arow = m0 + (lane & 15);
    int acol = (lane >> 4) << 3;
    int brow = (lane & 7) + ((lane >> 4) << 3);
    int bcol = ((lane >> 3) & 1) << 3;
    int cb = (lane & 3) * 2;
    int r0 = m0 + (lane >> 2);

    for (int tile = blockIdx.x; tile < N_TILES; tile += gridDim.x) {
        int rbase = tile * 128;

        for (int i = tid; i < 128 * 32; i += 256) {
            int r = i >> 5, c = i & 31;
            int row = rbase + r;
            uint2 v = make_uint2(0u, 0u);
            if (row < N_NODES) v = ((const uint2*)g_aggh)[(size_t)row * 32 + c];
            *(uint2*)&sm[SA_O + r * LDW + c * 4] = v;
        }
        __syncthreads();

        float acc[16][4];
        #pragma unroll
        for (int nt = 0; nt < 16; nt++) {
            float b0 = sBias[nt * 8 + cb], b1 = sBias[nt * 8 + cb + 1];
            acc[nt][0] = b0; acc[nt][1] = b1; acc[nt][2] = b0; acc[nt][3] = b1;
        }
        gemm_pass(acc, sbA, sb1, arow, acol, brow, bcol);
        __syncwarp();

        #pragma unroll
        for (int nt = 0; nt < 16; nt++) {
            int c = nt * 8 + cb;
            float h0 = softplus_f(acc[nt][0]);
            float h1 = softplus_f(acc[nt][1]);
            float h2 = softplus_f(acc[nt][2]);
            float h3 = softplus_f(acc[nt][3]);
            *(uint32_t*)&sm[SA_O + r0 * LDW + c]       = f16pack(h0, h1);
            *(uint32_t*)&sm[SA_O + (r0 + 8) * LDW + c] = f16pack(h2, h3);
        }
        __syncwarp();

        #pragma unroll
        for (int nt = 0; nt < 16; nt++) {
            acc[nt][0] = 0.f; acc[nt][1] = 0.f; acc[nt][2] = 0.f; acc[nt][3] = 0.f;
        }
        gemm_pass(acc, sbA, sb2, arow, acol, brow, bcol);

        int g0 = rbase + r0;
        #pragma unroll
        for (int nt = 0; nt < 16; nt++) {
            int c = nt * 8 + cb;
            float s0 = sScale[c], s1 = sScale[c + 1];
            float t0 = sShift[c], t1 = sShift[c + 1];
            if (g0 < N_NODES)
                *(float2*)&out[(size_t)g0 * 128 + c] =
                    make_float2(acc[nt][0] * s0 + t0, acc[nt][1] * s1 + t1);
            if (g0 + 8 < N_NODES)
                *(float2*)&out[(size_t)(g0 + 8) * 128 + c] =
                    make_float2(acc[nt][2] * s0 + t0, acc[nt][3] * s1 + t1);
        }
        __syncthreads();
    }
}

extern "C" void kernel_launch(void* const* d_in, const int* in_sizes, int n_in,
                              void* d_out, int out_size) {
    const float* x     = (const float*)d_in[0];
    const int*   ei    = (const int*)  d_in[1];
    const float* ew    = (const float*)d_in[2];
    const float* Wf1   = (const float*)d_in[4];
    const float* bf1   = (const float*)d_in[5];
    const float* Wf2   = (const float*)d_in[6];
    const float* bf2   = (const float*)d_in[7];
    const float* Wi1   = (const float*)d_in[8];
    const float* bi1   = (const float*)d_in[9];
    const float* Wi2   = (const float*)d_in[10];
    const float* bi2   = (const float*)d_in[11];
    const float* gamma = (const float*)d_in[12];
    const float* beta  = (const float*)d_in[13];
    const float* mmean = (const float*)d_in[14];
    const float* mvar  = (const float*)d_in[15];
    int E = in_sizes[2];
    float* out = (float*)d_out;

    int setup_grid = HIST_B0 + (E + 255) / 256;
    setup_kernel<<<setup_grid, 256>>>(x, ei, E, Wf1, bf1, Wf2, bf2, Wi1, Wi2,
                                      bi2, gamma, beta, mmean, mvar);
    scan12_kernel<<<NB, 256>>>();
    scan3_kernel<<<NB, 512>>>(E);
    reorder_kernel<<<(E + 255) / 256, 256>>>(ei, ew, E);
    aggregate_kernel<<<(N_NODES * 32 + 255) / 256, 256>>>();

    cudaFuncSetAttribute(mlp_mma_kernel, cudaFuncAttributeMaxDynamicSharedMemorySize,
                         SMEM_MMA);
    mlp_mma_kernel<<<296, 256, SMEM_MMA>>>(bi1, out);
}